// round 13
// baseline (speedup 1.0000x reference)
#include <cuda_runtime.h>
#include <stdint.h>
#include <math.h>

#define Bx 8
#define Cx 4
#define Hx 384
#define Wx 384
#define SLICE (Hx*Wx)          // 147456
#define NSLICE (Bx*Cx)         // 32
#define BIGI 768               // = H + W, finite sentinel (matches reference)
#define INFP 0x3FFF3FFFu       // packed u16x2 "infinity" (saturating math keeps it big)
#define ONEP 0x00010001u
#define PADSQ 0xFE01FE01u      // packed 255^2: pad candidates always lose (>9)
#define ROWS 4                 // rows per k_row block

// Scratch (no cudaMalloc allowed).
__device__ unsigned long long g_pack[Bx*SLICE]; // [b][h][w] -> g for 4 classes, u16x4 (9 MB)
__device__ unsigned int   g_dmax_bits[NSLICE];
__device__ double         g_S[NSLICE];          // sum of p_c over target pixels
__device__ double         g_acc;                // sum of p_c * dt over non-target pixels
__device__ unsigned int   g_count;              // zero-init; reset by last k_row block

__device__ __forceinline__ float sqrt_approx(float x) {
    float r;
    asm("sqrt.approx.f32 %0, %1;" : "=f"(r) : "f"(x));
    return r;
}

// ---------------------------------------------------------------------------
// Phase 1: vertical 1D distance per (b,w) column for ALL 4 classes packed
// u16x4. One warp per column; lane owns a 12-pixel h-segment. Exact segmented
// min-plus scan; unclamped math + final clamp(768) == reference's per-step
// clamp since increments are +1.
__global__ void __launch_bounds__(256) k_phase1(const int* __restrict__ targets) {
    __shared__ unsigned long long sg[Hx][9];   // 27 KB staging (pad vs bank conflicts)

    int tid = threadIdx.x, wid = tid >> 5, lane = tid & 31;
    if (blockIdx.x == 0 && tid < NSLICE) {     // fused init
        g_dmax_bits[tid] = 0u; g_S[tid] = 0.0;
        if (tid == 0) g_acc = 0.0;
    }

    int b  = blockIdx.x / (Wx / 8);
    int w0 = (blockIdx.x % (Wx / 8)) * 8;
    int w  = w0 + wid;
    const int* tb = targets + (size_t)b * SLICE + w;
    int h0 = lane * 12;

    uint32_t mlo[12], mhi[12];
    #pragma unroll
    for (int i = 0; i < 12; ++i) {
        int t = __ldg(&tb[(h0 + i) * Wx]);
        mlo[i] = (t == 0) ? 0xFFFF0000u : (t == 1) ? 0x0000FFFFu : 0xFFFFFFFFu;
        mhi[i] = (t == 2) ? 0xFFFF0000u : (t == 3) ? 0x0000FFFFu : 0xFFFFFFFFu;
    }

    uint32_t flo = INFP, fhi = INFP;
    #pragma unroll
    for (int i = 0; i < 12; ++i) { flo = __vaddus2(flo, ONEP) & mlo[i]; fhi = __vaddus2(fhi, ONEP) & mhi[i]; }
    uint32_t blo = INFP, bhi = INFP;
    #pragma unroll
    for (int i = 11; i >= 0; --i) { blo = __vaddus2(blo, ONEP) & mlo[i]; bhi = __vaddus2(bhi, ONEP) & mhi[i]; }

    uint32_t filo = flo, fihi = fhi, bilo = blo, bihi = bhi;
    #pragma unroll
    for (int d = 1; d < 32; d <<= 1) {
        uint32_t k = ((12u * d) << 16) | (12u * d);
        uint32_t a0 = __shfl_up_sync(0xffffffffu, filo, d);
        uint32_t a1 = __shfl_up_sync(0xffffffffu, fihi, d);
        if (lane >= d) { filo = __vminu2(filo, __vaddus2(a0, k)); fihi = __vminu2(fihi, __vaddus2(a1, k)); }
        uint32_t c0 = __shfl_down_sync(0xffffffffu, bilo, d);
        uint32_t c1 = __shfl_down_sync(0xffffffffu, bihi, d);
        if (lane < 32 - d) { bilo = __vminu2(bilo, __vaddus2(c0, k)); bihi = __vminu2(bihi, __vaddus2(c1, k)); }
    }
    uint32_t cflo = __shfl_up_sync(0xffffffffu, filo, 1);
    uint32_t cfhi = __shfl_up_sync(0xffffffffu, fihi, 1);
    if (lane == 0) { cflo = INFP; cfhi = INFP; }
    uint32_t cblo = __shfl_down_sync(0xffffffffu, bilo, 1);
    uint32_t cbhi = __shfl_down_sync(0xffffffffu, bihi, 1);
    if (lane == 31) { cblo = INFP; cbhi = INFP; }

    unsigned long long Df[12];
    uint32_t rlo = cflo, rhi = cfhi;
    flo = INFP; fhi = INFP;
    #pragma unroll
    for (int i = 0; i < 12; ++i) {
        rlo = __vaddus2(rlo, ONEP); rhi = __vaddus2(rhi, ONEP);
        flo = __vaddus2(flo, ONEP) & mlo[i]; fhi = __vaddus2(fhi, ONEP) & mhi[i];
        uint32_t xlo = __vminu2(flo, rlo), xhi = __vminu2(fhi, rhi);
        Df[i] = ((unsigned long long)xhi << 32) | xlo;
    }
    const uint32_t CLP = ((uint32_t)BIGI << 16) | (uint32_t)BIGI;
    rlo = cblo; rhi = cbhi; blo = INFP; bhi = INFP;
    #pragma unroll
    for (int i = 11; i >= 0; --i) {
        rlo = __vaddus2(rlo, ONEP); rhi = __vaddus2(rhi, ONEP);
        blo = __vaddus2(blo, ONEP) & mlo[i]; bhi = __vaddus2(bhi, ONEP) & mhi[i];
        uint32_t xlo = __vminu2(blo, rlo), xhi = __vminu2(bhi, rhi);
        xlo = __vminu2(__vminu2(xlo, (uint32_t)Df[i]), CLP);
        xhi = __vminu2(__vminu2(xhi, (uint32_t)(Df[i] >> 32)), CLP);
        sg[h0 + i][wid] = ((unsigned long long)xhi << 32) | xlo;
    }
    __syncthreads();

    unsigned long long* gp = g_pack + (size_t)b * SLICE;
    #pragma unroll
    for (int e = tid; e < Hx * 8; e += 256) {
        int h = e >> 3, wl = e & 7;
        gp[(size_t)h * Wx + w0 + wl] = sg[h][wl];
    }
}

// ---------------------------------------------------------------------------
// Rare exact tail for m > 9: full pruned scan from global packed g (unclamped).
__device__ __noinline__ int tail_m(const unsigned long long* gr, int y, int sh) {
    int v0 = (int)((gr[y] >> sh) & 0xFFFF);
    int m = v0 * v0;
    for (int r = 1; r < Wx && r * r < m; ++r) {
        int jl = y - r, jr = y + r;
        if (jl >= 0) { int v = (int)((gr[jl] >> sh) & 0xFFFF); m = min(m, v * v + r * r); }
        if (jr < Wx) { int v = (int)((gr[jr] >> sh) & 0xFFFF); m = min(m, v * v + r * r); }
    }
    return m;
}

// ---------------------------------------------------------------------------
// Phase 2+3 fused + finalization: one 128-thread block per (b, 4-row band),
// all 4 classes, branch-free per pixel. MUFU-minimized: 3 exps (softmax shift
// by l3 -- shift invariance), 1 rcp, sqrt via 10-entry shared LUT (m is an
// integer <= 9 on the fast path; tail keeps sqrt.approx).
//   dt_c(y) = sqrt( min_j g_c(j)^2 + (y-j)^2 )
// Fast path: m_f = min over |r|<=2 of min(g,255)^2 + r^2 (u16x2 SIMD). Exact
// when m_f <= 9 (every excluded candidate -- r>=3 or clamped g>=255 -- has
// value >= 9); else rare exact tail. dt at target class is 0 -> acc branchless.
__global__ void __launch_bounds__(128) k_row(const float* __restrict__ outputs,
                                             const int*   __restrict__ targets,
                                             float*       __restrict__ out) {
    __shared__ uint2 s_p[ROWS][Wx + 8];   // {p01,p23} per pixel, +-4 pad; 12.5 KB
    __shared__ float s_sqrt[16];          // sqrt LUT for m in 0..9
    __shared__ float s_red[4][9];
    __shared__ int s_last;

    int band = blockIdx.x;             // 0 .. B*H/ROWS-1
    int b    = band / (Hx / ROWS);
    int h0   = (band % (Hx / ROWS)) * ROWS;

    if (threadIdx.x < 16) s_sqrt[threadIdx.x] = sqrt_approx((float)threadIdx.x);

    const unsigned long long* gband = g_pack + (size_t)b * SLICE + (size_t)h0 * Wx;

    // build clamped-square packed arrays for the 4 rows
    for (int i = threadIdx.x; i < ROWS * Wx; i += 128) {
        int r = i / Wx, x = i - r * Wx;
        unsigned long long v = gband[i];
        int v0 = min((int)(v & 0xFFFF), 255);
        int v1 = min((int)((v >> 16) & 0xFFFF), 255);
        int v2 = min((int)((v >> 32) & 0xFFFF), 255);
        int v3 = min((int)((v >> 48) & 0xFFFF), 255);
        s_p[r][4 + x] = make_uint2((uint32_t)(v0 * v0) | ((uint32_t)(v1 * v1) << 16),
                                   (uint32_t)(v2 * v2) | ((uint32_t)(v3 * v3) << 16));
    }
    if (threadIdx.x < ROWS * 8) {
        int r = threadIdx.x >> 3, o = threadIdx.x & 7;
        int idx = (o < 4) ? o : (Wx + o);
        s_p[r][idx] = make_uint2(PADSQ, PADSQ);
    }
    __syncthreads();

    float acc = 0.0f;
    float Sv[Cx] = {0.0f, 0.0f, 0.0f, 0.0f};
    int   Mm[Cx] = {0, 0, 0, 0};            // per-class max of m (sqrt monotone)

    #pragma unroll
    for (int rw = 0; rw < ROWS; ++rw) {
        const float* ob = outputs + (size_t)b * Cx * SLICE + (size_t)(h0 + rw) * Wx;
        const int*   tb = targets + (size_t)b * SLICE + (size_t)(h0 + rw) * Wx;
        const unsigned long long* gr = gband + (size_t)rw * Wx;

        #pragma unroll
        for (int k = 0; k < Wx / 128; ++k) {
            int y = threadIdx.x + k * 128;

            float l0 = ob[y];
            float l1 = ob[y + SLICE];
            float l2 = ob[y + 2 * SLICE];
            float l3 = ob[y + 3 * SLICE];
            int   t  = tb[y];
            // softmax shifted by l3: e3 = 1 (one fewer exp; shift-invariant)
            float e0 = __expf(l0 - l3);
            float e1 = __expf(l1 - l3);
            float e2 = __expf(l2 - l3);
            float inv = __fdividef(1.0f, e0 + e1 + e2 + 1.0f);

            // packed 4-class scan, radii 0..2 (branch-free), uint2 LDS
            const uint2* P = &s_p[rw][4 + y];
            uint2 q0 = P[0];
            uint32_t m01 = q0.x, m23 = q0.y;
            const uint32_t K1 = 0x00010001u, K2 = 0x00040004u;
            uint2 qa = P[-1], qb = P[1];
            m01 = __vminu2(m01, __vaddus2(qa.x, K1));
            m23 = __vminu2(m23, __vaddus2(qa.y, K1));
            m01 = __vminu2(m01, __vaddus2(qb.x, K1));
            m23 = __vminu2(m23, __vaddus2(qb.y, K1));
            qa = P[-2]; qb = P[2];
            m01 = __vminu2(m01, __vaddus2(qa.x, K2));
            m23 = __vminu2(m23, __vaddus2(qa.y, K2));
            m01 = __vminu2(m01, __vaddus2(qb.x, K2));
            m23 = __vminu2(m23, __vaddus2(qb.y, K2));

            int m0 = (int)(m01 & 0xFFFFu), m1 = (int)(m01 >> 16);
            int m2 = (int)(m23 & 0xFFFFu), m3 = (int)(m23 >> 16);
            float d0, d1, d2, d3;
            if (__builtin_expect(max(max(m0, m1), max(m2, m3)) > 9, 0)) {  // rare
                if (m0 > 9) m0 = tail_m(gr, y, 0);
                if (m1 > 9) m1 = tail_m(gr, y, 16);
                if (m2 > 9) m2 = tail_m(gr, y, 32);
                if (m3 > 9) m3 = tail_m(gr, y, 48);
                d0 = sqrt_approx((float)m0);
                d1 = sqrt_approx((float)m1);
                d2 = sqrt_approx((float)m2);
                d3 = sqrt_approx((float)m3);
            } else {                                    // LUT: no MUFU
                d0 = s_sqrt[m0];
                d1 = s_sqrt[m1];
                d2 = s_sqrt[m2];
                d3 = s_sqrt[m3];
            }

            acc += (e0 * d0 + e1 * d1 + e2 * d2 + d3) * inv;  // dt at target = 0
            Sv[0] += (t == 0) ? e0 * inv : 0.0f;
            Sv[1] += (t == 1) ? e1 * inv : 0.0f;
            Sv[2] += (t == 2) ? e2 * inv : 0.0f;
            Sv[3] += (t == 3) ? inv      : 0.0f;
            Mm[0] = max(Mm[0], m0);
            Mm[1] = max(Mm[1], m1);
            Mm[2] = max(Mm[2], m2);
            Mm[3] = max(Mm[3], m3);
        }
    }

    // block reduction (sqrt is monotone -> reduce m as int, sqrt once)
    float Lm[Cx];
    #pragma unroll
    for (int c = 0; c < Cx; ++c) Lm[c] = sqrt_approx((float)Mm[c]);
    #pragma unroll
    for (int off = 16; off > 0; off >>= 1) {
        acc += __shfl_down_sync(0xffffffffu, acc, off);
        #pragma unroll
        for (int c = 0; c < Cx; ++c) {
            Sv[c] += __shfl_down_sync(0xffffffffu, Sv[c], off);
            Lm[c]  = fmaxf(Lm[c], __shfl_down_sync(0xffffffffu, Lm[c], off));
        }
    }
    int wid = threadIdx.x >> 5;
    if ((threadIdx.x & 31) == 0) {
        s_red[wid][0] = acc;
        #pragma unroll
        for (int c = 0; c < Cx; ++c) { s_red[wid][1 + c] = Sv[c]; s_red[wid][5 + c] = Lm[c]; }
    }
    __syncthreads();
    if (threadIdx.x < Cx) {                 // threads 0..3: one class each
        int c = threadIdx.x;
        float s = s_red[0][1 + c] + s_red[1][1 + c] + s_red[2][1 + c] + s_red[3][1 + c];
        float m = fmaxf(fmaxf(s_red[0][5 + c], s_red[1][5 + c]),
                        fmaxf(s_red[2][5 + c], s_red[3][5 + c]));
        atomicAdd(&g_S[b * Cx + c], (double)s);
        atomicMax(&g_dmax_bits[b * Cx + c], __float_as_uint(m));
        if (c == 0) {
            double a = (double)s_red[0][0] + s_red[1][0] + s_red[2][0] + s_red[3][0];
            atomicAdd(&g_acc, a);
        }
        __threadfence();                    // release this block's contributions
    }
    __syncthreads();
    if (threadIdx.x == 0)
        s_last = (atomicAdd(&g_count, 1u) == (unsigned)(gridDim.x - 1));
    __syncthreads();

    if (s_last && threadIdx.x < 32) {
        __threadfence();                    // acquire all blocks' contributions
        double v = (double)__uint_as_float(((volatile unsigned int*)g_dmax_bits)[threadIdx.x])
                 * ((volatile double*)g_S)[threadIdx.x];
        #pragma unroll
        for (int off = 16; off > 0; off >>= 1)
            v += __shfl_down_sync(0xffffffffu, v, off);
        if (threadIdx.x == 0) {
            double a = *((volatile double*)&g_acc);
            out[0] = (float)((a - v) / ((double)Cx * (double)Bx * Cx * Hx * Wx));
            g_count = 0u;                   // reset for next (graph) replay
        }
    }
}

// ---------------------------------------------------------------------------
extern "C" void kernel_launch(void* const* d_in, const int* in_sizes, int n_in,
                              void* d_out, int out_size) {
    const float* outputs = (const float*)d_in[0];
    const int*   targets = (const int*)d_in[1];
    float*       out     = (float*)d_out;

    k_phase1<<<Bx * (Wx / 8), 256>>>(targets);
    k_row<<<Bx * Hx / ROWS, 128>>>(outputs, targets, out);
}

// round 14
// speedup vs baseline: 1.0698x; 1.0698x over previous
#include <cuda_runtime.h>
#include <stdint.h>
#include <math.h>

#define Bx 8
#define Cx 4
#define Hx 384
#define Wx 384
#define SLICE (Hx*Wx)          // 147456
#define NSLICE (Bx*Cx)         // 32
#define BIGI 768               // = H + W, finite sentinel (matches reference)
#define INFP 0x3FFF3FFFu       // packed u16x2 "infinity" (saturating math keeps it big)
#define ONEP 0x00010001u
#define PADSQ 0xFE01FE01u      // packed 255^2: pad candidates always lose (>16)
#define ROWS 4                 // rows per band
#define GRID (Bx*Hx/ROWS)      // 768 blocks: == Bx*(Wx/4) for phase 1 as well

// Scratch (no cudaMalloc allowed).
__device__ unsigned long long g_pack[Bx*SLICE]; // [b][h][w] -> g for 4 classes, u16x4 (9 MB)
__device__ unsigned int   g_dmax_bits[NSLICE];
__device__ double         g_S[NSLICE];          // sum of p_c over target pixels
__device__ double         g_acc;                // sum of p_c * dt over non-target pixels
__device__ unsigned int   g_bar;                // soft global barrier (reset by last block)
__device__ unsigned int   g_count;              // finalization counter (reset by last block)

__device__ __forceinline__ float sqrt_approx(float x) {
    float r;
    asm("sqrt.approx.f32 %0, %1;" : "=f"(r) : "f"(x));
    return r;
}

// ---------------------------------------------------------------------------
// Rare exact tail for m > 16: full pruned scan from global packed g.
__device__ __noinline__ int tail_m(const unsigned long long* gr, int y, int sh) {
    int v0 = (int)((gr[y] >> sh) & 0xFFFF);
    int m = v0 * v0;
    for (int r = 1; r < Wx && r * r < m; ++r) {
        int jl = y - r, jr = y + r;
        if (jl >= 0) { int v = (int)((gr[jl] >> sh) & 0xFFFF); m = min(m, v * v + r * r); }
        if (jr < Wx) { int v = (int)((gr[jr] >> sh) & 0xFFFF); m = min(m, v * v + r * r); }
    }
    return m;
}

// ---------------------------------------------------------------------------
// ONE fused kernel. 768 co-resident blocks (launch_bounds(128,6): 6x148=888
// >= 768, smem 15.5KB*6 = 93KB < 228KB -> software barrier is deadlock-free).
//
// Part 1 (per block: 4 columns of one batch): vertical 1D distance for all 4
// classes packed u16x4 via exact warp-level segmented min-plus scan (one warp
// per (b,w) column; lane owns a 12-pixel h-segment). Unclamped math + final
// clamp(768) == reference per-step clamp (increments are +1).
//
// Global barrier (atomic counter + fences; all blocks resident).
//
// Part 2 (per block: one (b, 4-row band)): dt_c(y) = sqrt(min_j g_c(j)^2 +
// (y-j)^2). Fast path: min over |r|<=3 of min(g,255)^2 + r^2, 4 classes via
// u16x2 SIMD. Exact when m <= 16 (every excluded candidate -- r>=4 or clamped
// g>=255 -- has value >= 16; ties at 16 don't change the min); else rare
// exact tail (~0.03% pixels). Softmax shifted by l3 (e3=1, shift-invariant).
// dt at target class is 0 -> acc is branch-free. Last block finalizes:
//   loss = ( sum p_c*dt_c  -  sum_s dmax_s*S_s ) / (C * B*C*H*W).
__global__ void __launch_bounds__(128, 6) k_fused(const float* __restrict__ outputs,
                                                  const int*   __restrict__ targets,
                                                  float*       __restrict__ out) {
    __shared__ __align__(16) unsigned char s_buf[Hx * 5 * 8];   // 15360 B, reused
    __shared__ float s_red[4][9];
    __shared__ int s_last;

    int tid = threadIdx.x, wid = tid >> 5, lane = tid & 31;

    if (blockIdx.x == 0 && tid < NSLICE) {     // init (consumed after barrier)
        g_dmax_bits[tid] = 0u; g_S[tid] = 0.0;
        if (tid == 0) g_acc = 0.0;
    }

    // ================= Part 1: vertical scans (4 columns per block) =========
    {
        unsigned long long (*sg)[5] = (unsigned long long (*)[5])s_buf;
        int b  = blockIdx.x / (Wx / 4);
        int w0 = (blockIdx.x % (Wx / 4)) * 4;
        int w  = w0 + wid;
        const int* tb = targets + (size_t)b * SLICE + w;
        int h0 = lane * 12;

        uint32_t mlo[12], mhi[12];
        #pragma unroll
        for (int i = 0; i < 12; ++i) {
            int t = __ldg(&tb[(h0 + i) * Wx]);
            mlo[i] = (t == 0) ? 0xFFFF0000u : (t == 1) ? 0x0000FFFFu : 0xFFFFFFFFu;
            mhi[i] = (t == 2) ? 0xFFFF0000u : (t == 3) ? 0x0000FFFFu : 0xFFFFFFFFu;
        }

        uint32_t flo = INFP, fhi = INFP;
        #pragma unroll
        for (int i = 0; i < 12; ++i) { flo = __vaddus2(flo, ONEP) & mlo[i]; fhi = __vaddus2(fhi, ONEP) & mhi[i]; }
        uint32_t blo = INFP, bhi = INFP;
        #pragma unroll
        for (int i = 11; i >= 0; --i) { blo = __vaddus2(blo, ONEP) & mlo[i]; bhi = __vaddus2(bhi, ONEP) & mhi[i]; }

        uint32_t filo = flo, fihi = fhi, bilo = blo, bihi = bhi;
        #pragma unroll
        for (int d = 1; d < 32; d <<= 1) {
            uint32_t k = ((12u * d) << 16) | (12u * d);
            uint32_t a0 = __shfl_up_sync(0xffffffffu, filo, d);
            uint32_t a1 = __shfl_up_sync(0xffffffffu, fihi, d);
            if (lane >= d) { filo = __vminu2(filo, __vaddus2(a0, k)); fihi = __vminu2(fihi, __vaddus2(a1, k)); }
            uint32_t c0 = __shfl_down_sync(0xffffffffu, bilo, d);
            uint32_t c1 = __shfl_down_sync(0xffffffffu, bihi, d);
            if (lane < 32 - d) { bilo = __vminu2(bilo, __vaddus2(c0, k)); bihi = __vminu2(bihi, __vaddus2(c1, k)); }
        }
        uint32_t cflo = __shfl_up_sync(0xffffffffu, filo, 1);
        uint32_t cfhi = __shfl_up_sync(0xffffffffu, fihi, 1);
        if (lane == 0) { cflo = INFP; cfhi = INFP; }
        uint32_t cblo = __shfl_down_sync(0xffffffffu, bilo, 1);
        uint32_t cbhi = __shfl_down_sync(0xffffffffu, bihi, 1);
        if (lane == 31) { cblo = INFP; cbhi = INFP; }

        unsigned long long Df[12];
        uint32_t rlo = cflo, rhi = cfhi;
        flo = INFP; fhi = INFP;
        #pragma unroll
        for (int i = 0; i < 12; ++i) {
            rlo = __vaddus2(rlo, ONEP); rhi = __vaddus2(rhi, ONEP);
            flo = __vaddus2(flo, ONEP) & mlo[i]; fhi = __vaddus2(fhi, ONEP) & mhi[i];
            uint32_t xlo = __vminu2(flo, rlo), xhi = __vminu2(fhi, rhi);
            Df[i] = ((unsigned long long)xhi << 32) | xlo;
        }
        const uint32_t CLP = ((uint32_t)BIGI << 16) | (uint32_t)BIGI;
        rlo = cblo; rhi = cbhi; blo = INFP; bhi = INFP;
        #pragma unroll
        for (int i = 11; i >= 0; --i) {
            rlo = __vaddus2(rlo, ONEP); rhi = __vaddus2(rhi, ONEP);
            blo = __vaddus2(blo, ONEP) & mlo[i]; bhi = __vaddus2(bhi, ONEP) & mhi[i];
            uint32_t xlo = __vminu2(blo, rlo), xhi = __vminu2(bhi, rhi);
            xlo = __vminu2(__vminu2(xlo, (uint32_t)Df[i]), CLP);
            xhi = __vminu2(__vminu2(xhi, (uint32_t)(Df[i] >> 32)), CLP);
            sg[h0 + i][wid] = ((unsigned long long)xhi << 32) | xlo;
        }
        __syncthreads();

        unsigned long long* gp = g_pack + (size_t)b * SLICE;
        #pragma unroll
        for (int e = tid; e < Hx * 4; e += 128) {
            int h = e >> 2, wl = e & 3;
            gp[(size_t)h * Wx + w0 + wl] = sg[h][wl];
        }
    }

    // ================= Global barrier (all 768 blocks resident) =============
    __syncthreads();
    if (tid == 0) {
        __threadfence();                          // release g_pack writes
        atomicAdd(&g_bar, 1u);
        while (*(volatile unsigned int*)&g_bar < (unsigned)gridDim.x)
            __nanosleep(64);
    }
    __syncthreads();
    __threadfence();                              // acquire all g_pack writes

    // ================= Part 2: row EDT + softmax + reductions ===============
    uint2 (*s_p)[Wx + 8] = (uint2 (*)[Wx + 8])s_buf;   // [ROWS][Wx+8], 12.5 KB

    int band = blockIdx.x;
    int b    = band / (Hx / ROWS);
    int h0   = (band % (Hx / ROWS)) * ROWS;

    const unsigned long long* gband = g_pack + (size_t)b * SLICE + (size_t)h0 * Wx;

    for (int i = tid; i < ROWS * Wx; i += 128) {
        int r = i / Wx, x = i - r * Wx;
        unsigned long long v = gband[i];
        int v0 = min((int)(v & 0xFFFF), 255);
        int v1 = min((int)((v >> 16) & 0xFFFF), 255);
        int v2 = min((int)((v >> 32) & 0xFFFF), 255);
        int v3 = min((int)((v >> 48) & 0xFFFF), 255);
        s_p[r][4 + x] = make_uint2((uint32_t)(v0 * v0) | ((uint32_t)(v1 * v1) << 16),
                                   (uint32_t)(v2 * v2) | ((uint32_t)(v3 * v3) << 16));
    }
    if (tid < ROWS * 8) {
        int r = tid >> 3, o = tid & 7;
        int idx = (o < 4) ? o : (Wx + o);
        s_p[r][idx] = make_uint2(PADSQ, PADSQ);
    }
    __syncthreads();

    float acc = 0.0f;
    float Sv[Cx] = {0.0f, 0.0f, 0.0f, 0.0f};
    int   Mm[Cx] = {0, 0, 0, 0};            // per-class max of m (sqrt monotone)

    #pragma unroll
    for (int rw = 0; rw < ROWS; ++rw) {
        const float* ob = outputs + (size_t)b * Cx * SLICE + (size_t)(h0 + rw) * Wx;
        const int*   tb = targets + (size_t)b * SLICE + (size_t)(h0 + rw) * Wx;
        const unsigned long long* gr = gband + (size_t)rw * Wx;

        #pragma unroll
        for (int k = 0; k < Wx / 128; ++k) {
            int y = tid + k * 128;

            float l0 = ob[y];
            float l1 = ob[y + SLICE];
            float l2 = ob[y + 2 * SLICE];
            float l3 = ob[y + 3 * SLICE];
            int   t  = tb[y];
            float e0 = __expf(l0 - l3);           // shift-invariant softmax, e3=1
            float e1 = __expf(l1 - l3);
            float e2 = __expf(l2 - l3);
            float inv = __fdividef(1.0f, e0 + e1 + e2 + 1.0f);

            // packed 4-class scan, radii 0..3 (branch-free), uint2 LDS
            const uint2* P = &s_p[rw][4 + y];
            uint2 q0 = P[0];
            uint32_t m01 = q0.x, m23 = q0.y;
            const uint32_t K1 = 0x00010001u, K2 = 0x00040004u, K3 = 0x00090009u;
            uint2 qa = P[-1], qb = P[1];
            m01 = __vminu2(m01, __vaddus2(qa.x, K1));
            m23 = __vminu2(m23, __vaddus2(qa.y, K1));
            m01 = __vminu2(m01, __vaddus2(qb.x, K1));
            m23 = __vminu2(m23, __vaddus2(qb.y, K1));
            qa = P[-2]; qb = P[2];
            m01 = __vminu2(m01, __vaddus2(qa.x, K2));
            m23 = __vminu2(m23, __vaddus2(qa.y, K2));
            m01 = __vminu2(m01, __vaddus2(qb.x, K2));
            m23 = __vminu2(m23, __vaddus2(qb.y, K2));
            qa = P[-3]; qb = P[3];
            m01 = __vminu2(m01, __vaddus2(qa.x, K3));
            m23 = __vminu2(m23, __vaddus2(qa.y, K3));
            m01 = __vminu2(m01, __vaddus2(qb.x, K3));
            m23 = __vminu2(m23, __vaddus2(qb.y, K3));

            int m0 = (int)(m01 & 0xFFFFu), m1 = (int)(m01 >> 16);
            int m2 = (int)(m23 & 0xFFFFu), m3 = (int)(m23 >> 16);
            if (__builtin_expect(max(max(m0, m1), max(m2, m3)) > 16, 0)) {  // rare
                if (m0 > 16) m0 = tail_m(gr, y, 0);
                if (m1 > 16) m1 = tail_m(gr, y, 16);
                if (m2 > 16) m2 = tail_m(gr, y, 32);
                if (m3 > 16) m3 = tail_m(gr, y, 48);
            }
            float d0 = sqrt_approx((float)m0);
            float d1 = sqrt_approx((float)m1);
            float d2 = sqrt_approx((float)m2);
            float d3 = sqrt_approx((float)m3);

            acc += (e0 * d0 + e1 * d1 + e2 * d2 + d3) * inv;  // dt at target = 0
            Sv[0] += (t == 0) ? e0 * inv : 0.0f;
            Sv[1] += (t == 1) ? e1 * inv : 0.0f;
            Sv[2] += (t == 2) ? e2 * inv : 0.0f;
            Sv[3] += (t == 3) ? inv      : 0.0f;
            Mm[0] = max(Mm[0], m0);
            Mm[1] = max(Mm[1], m1);
            Mm[2] = max(Mm[2], m2);
            Mm[3] = max(Mm[3], m3);
        }
    }

    // block reduction (sqrt is monotone -> reduce m as int, sqrt once)
    float Lm[Cx];
    #pragma unroll
    for (int c = 0; c < Cx; ++c) Lm[c] = sqrt_approx((float)Mm[c]);
    #pragma unroll
    for (int off = 16; off > 0; off >>= 1) {
        acc += __shfl_down_sync(0xffffffffu, acc, off);
        #pragma unroll
        for (int c = 0; c < Cx; ++c) {
            Sv[c] += __shfl_down_sync(0xffffffffu, Sv[c], off);
            Lm[c]  = fmaxf(Lm[c], __shfl_down_sync(0xffffffffu, Lm[c], off));
        }
    }
    if (lane == 0) {
        s_red[wid][0] = acc;
        #pragma unroll
        for (int c = 0; c < Cx; ++c) { s_red[wid][1 + c] = Sv[c]; s_red[wid][5 + c] = Lm[c]; }
    }
    __syncthreads();
    if (tid < Cx) {                         // threads 0..3: one class each
        int c = tid;
        float s = s_red[0][1 + c] + s_red[1][1 + c] + s_red[2][1 + c] + s_red[3][1 + c];
        float m = fmaxf(fmaxf(s_red[0][5 + c], s_red[1][5 + c]),
                        fmaxf(s_red[2][5 + c], s_red[3][5 + c]));
        atomicAdd(&g_S[b * Cx + c], (double)s);
        atomicMax(&g_dmax_bits[b * Cx + c], __float_as_uint(m));
        if (c == 0) {
            double a = (double)s_red[0][0] + s_red[1][0] + s_red[2][0] + s_red[3][0];
            atomicAdd(&g_acc, a);
        }
        __threadfence();                    // release this block's contributions
    }
    __syncthreads();
    if (tid == 0)
        s_last = (atomicAdd(&g_count, 1u) == (unsigned)(gridDim.x - 1));
    __syncthreads();

    if (s_last && tid < 32) {
        __threadfence();                    // acquire all blocks' contributions
        double v = (double)__uint_as_float(((volatile unsigned int*)g_dmax_bits)[tid])
                 * ((volatile double*)g_S)[tid];
        #pragma unroll
        for (int off = 16; off > 0; off >>= 1)
            v += __shfl_down_sync(0xffffffffu, v, off);
        if (tid == 0) {
            double a = *((volatile double*)&g_acc);
            out[0] = (float)((a - v) / ((double)Cx * (double)Bx * Cx * Hx * Wx));
            g_count = 0u;                   // reset for next (graph) replay
            g_bar   = 0u;                   // safe: every block passed the barrier
        }
    }
}

// ---------------------------------------------------------------------------
extern "C" void kernel_launch(void* const* d_in, const int* in_sizes, int n_in,
                              void* d_out, int out_size) {
    const float* outputs = (const float*)d_in[0];
    const int*   targets = (const int*)d_in[1];
    float*       out     = (float*)d_out;

    k_fused<<<GRID, 128>>>(outputs, targets, out);
}

// round 15
// speedup vs baseline: 1.1012x; 1.0294x over previous
#include <cuda_runtime.h>
#include <stdint.h>
#include <math.h>

#define Bx 8
#define Cx 4
#define Hx 384
#define Wx 384
#define SLICE (Hx*Wx)          // 147456
#define NSLICE (Bx*Cx)         // 32
#define BIGI 768               // = H + W, finite sentinel (matches reference)
#define INFP 0x3FFF3FFFu       // packed u16x2 "infinity" (saturating math keeps it big)
#define ONEP 0x00010001u
#define PADSQ 0xFE01FE01u      // packed 255^2 halves: pad candidates always lose (>16)
#define ROWS 4                 // rows per k_row block

// Scratch (no cudaMalloc allowed).
__device__ unsigned long long g_pack[Bx*SLICE]; // [b][h][w] -> g for 4 classes, u16x4 (9 MB)
__device__ unsigned int   g_dmax_bits[NSLICE];
__device__ double         g_S[NSLICE];          // sum of p_c over target pixels
__device__ double         g_acc;                // sum of p_c * dt over non-target pixels
__device__ unsigned int   g_count;              // zero-init; reset by last k_row block

__device__ __forceinline__ float sqrt_approx(float x) {
    float r;
    asm("sqrt.approx.f32 %0, %1;" : "=f"(r) : "f"(x));
    return r;
}

// ---------------------------------------------------------------------------
// Phase 1: vertical 1D distance per (b,w) column for ALL 4 classes packed
// u16x4. One warp per column; lane owns a 12-pixel h-segment. Exact segmented
// min-plus scan; unclamped math + final clamp(768) == reference's per-step
// clamp since increments are +1.
__global__ void __launch_bounds__(256) k_phase1(const int* __restrict__ targets) {
    __shared__ unsigned long long sg[Hx][9];   // 27 KB staging (pad vs bank conflicts)

    int tid = threadIdx.x, wid = tid >> 5, lane = tid & 31;
    if (blockIdx.x == 0 && tid < NSLICE) {     // fused init
        g_dmax_bits[tid] = 0u; g_S[tid] = 0.0;
        if (tid == 0) g_acc = 0.0;
    }

    int b  = blockIdx.x / (Wx / 8);
    int w0 = (blockIdx.x % (Wx / 8)) * 8;
    int w  = w0 + wid;
    const int* tb = targets + (size_t)b * SLICE + w;
    int h0 = lane * 12;

    uint32_t mlo[12], mhi[12];
    #pragma unroll
    for (int i = 0; i < 12; ++i) {
        int t = __ldg(&tb[(h0 + i) * Wx]);
        mlo[i] = (t == 0) ? 0xFFFF0000u : (t == 1) ? 0x0000FFFFu : 0xFFFFFFFFu;
        mhi[i] = (t == 2) ? 0xFFFF0000u : (t == 3) ? 0x0000FFFFu : 0xFFFFFFFFu;
    }

    uint32_t flo = INFP, fhi = INFP;
    #pragma unroll
    for (int i = 0; i < 12; ++i) { flo = __vaddus2(flo, ONEP) & mlo[i]; fhi = __vaddus2(fhi, ONEP) & mhi[i]; }
    uint32_t blo = INFP, bhi = INFP;
    #pragma unroll
    for (int i = 11; i >= 0; --i) { blo = __vaddus2(blo, ONEP) & mlo[i]; bhi = __vaddus2(bhi, ONEP) & mhi[i]; }

    uint32_t filo = flo, fihi = fhi, bilo = blo, bihi = bhi;
    #pragma unroll
    for (int d = 1; d < 32; d <<= 1) {
        uint32_t k = ((12u * d) << 16) | (12u * d);
        uint32_t a0 = __shfl_up_sync(0xffffffffu, filo, d);
        uint32_t a1 = __shfl_up_sync(0xffffffffu, fihi, d);
        if (lane >= d) { filo = __vminu2(filo, __vaddus2(a0, k)); fihi = __vminu2(fihi, __vaddus2(a1, k)); }
        uint32_t c0 = __shfl_down_sync(0xffffffffu, bilo, d);
        uint32_t c1 = __shfl_down_sync(0xffffffffu, bihi, d);
        if (lane < 32 - d) { bilo = __vminu2(bilo, __vaddus2(c0, k)); bihi = __vminu2(bihi, __vaddus2(c1, k)); }
    }
    uint32_t cflo = __shfl_up_sync(0xffffffffu, filo, 1);
    uint32_t cfhi = __shfl_up_sync(0xffffffffu, fihi, 1);
    if (lane == 0) { cflo = INFP; cfhi = INFP; }
    uint32_t cblo = __shfl_down_sync(0xffffffffu, bilo, 1);
    uint32_t cbhi = __shfl_down_sync(0xffffffffu, bihi, 1);
    if (lane == 31) { cblo = INFP; cbhi = INFP; }

    unsigned long long Df[12];
    uint32_t rlo = cflo, rhi = cfhi;
    flo = INFP; fhi = INFP;
    #pragma unroll
    for (int i = 0; i < 12; ++i) {
        rlo = __vaddus2(rlo, ONEP); rhi = __vaddus2(rhi, ONEP);
        flo = __vaddus2(flo, ONEP) & mlo[i]; fhi = __vaddus2(fhi, ONEP) & mhi[i];
        uint32_t xlo = __vminu2(flo, rlo), xhi = __vminu2(fhi, rhi);
        Df[i] = ((unsigned long long)xhi << 32) | xlo;
    }
    const uint32_t CLP = ((uint32_t)BIGI << 16) | (uint32_t)BIGI;
    rlo = cblo; rhi = cbhi; blo = INFP; bhi = INFP;
    #pragma unroll
    for (int i = 11; i >= 0; --i) {
        rlo = __vaddus2(rlo, ONEP); rhi = __vaddus2(rhi, ONEP);
        blo = __vaddus2(blo, ONEP) & mlo[i]; bhi = __vaddus2(bhi, ONEP) & mhi[i];
        uint32_t xlo = __vminu2(blo, rlo), xhi = __vminu2(bhi, rhi);
        xlo = __vminu2(__vminu2(xlo, (uint32_t)Df[i]), CLP);
        xhi = __vminu2(__vminu2(xhi, (uint32_t)(Df[i] >> 32)), CLP);
        sg[h0 + i][wid] = ((unsigned long long)xhi << 32) | xlo;
    }
    __syncthreads();

    unsigned long long* gp = g_pack + (size_t)b * SLICE;
    #pragma unroll
    for (int e = tid; e < Hx * 8; e += 256) {
        int h = e >> 3, wl = e & 7;
        gp[(size_t)h * Wx + w0 + wl] = sg[h][wl];
    }
}

// ---------------------------------------------------------------------------
// Rare exact tail for m > 16: full pruned scan from global packed g.
__device__ __noinline__ int tail_m(const unsigned long long* gr, int y, int sh) {
    int v0 = (int)((gr[y] >> sh) & 0xFFFF);
    int m = v0 * v0;
    for (int r = 1; r < Wx && r * r < m; ++r) {
        int jl = y - r, jr = y + r;
        if (jl >= 0) { int v = (int)((gr[jl] >> sh) & 0xFFFF); m = min(m, v * v + r * r); }
        if (jr < Wx) { int v = (int)((gr[jr] >> sh) & 0xFFFF); m = min(m, v * v + r * r); }
    }
    return m;
}

// ---------------------------------------------------------------------------
// Phase 2+3 fused + finalization: one 128-thread block per (b, 4-row band).
// Each thread handles 4 CONSECUTIVE pixels -> float4/int4 global loads, and
// the overlapping radius-3 windows of the 4 pixels are covered by 3 aligned
// uint4 LDS.128 per class-pair array (conflict-free: 16B lane stride).
//   dt_c(y) = sqrt( min_j g_c(j)^2 + (y-j)^2 )
// Fast path: min over |r|<=3 of min(g,255)^2 + r^2 via u16x2 SIMD. Exact when
// m <= 16 (every excluded candidate -- r>=4 or clamped g>=255 -- has value
// >= 16; ties at 16 leave the min unchanged); else rare exact tail (~0.03%).
// Softmax shifted by l3 (e3 = 1, shift-invariant). dt at target class is 0,
// so acc is branch-free. Last block (counter) finalizes:
//   loss = ( sum p_c*dt_c - sum_s dmax_s*S_s ) / (C * B*C*H*W).
__global__ void __launch_bounds__(128, 6) k_row(const float* __restrict__ outputs,
                                                const int*   __restrict__ targets,
                                                float*       __restrict__ out) {
    __shared__ uint32_t s01[ROWS][Wx + 8];   // sq(c0)|sq(c1)<<16, +-4 pad; 6.1 KB
    __shared__ uint32_t s23[ROWS][Wx + 8];   // sq(c2)|sq(c3)<<16
    __shared__ float s_red[4][9];
    __shared__ int s_last;

    int tid  = threadIdx.x;
    int band = blockIdx.x;             // 0 .. B*H/ROWS-1
    int b    = band / (Hx / ROWS);
    int h0   = (band % (Hx / ROWS)) * ROWS;

    const unsigned long long* gband = g_pack + (size_t)b * SLICE + (size_t)h0 * Wx;

    // build clamped-square packed arrays for the 4 rows
    for (int i = tid; i < ROWS * Wx; i += 128) {
        int r = i / Wx, x = i - r * Wx;
        unsigned long long v = gband[i];
        int v0 = min((int)(v & 0xFFFF), 255);
        int v1 = min((int)((v >> 16) & 0xFFFF), 255);
        int v2 = min((int)((v >> 32) & 0xFFFF), 255);
        int v3 = min((int)((v >> 48) & 0xFFFF), 255);
        s01[r][4 + x] = (uint32_t)(v0 * v0) | ((uint32_t)(v1 * v1) << 16);
        s23[r][4 + x] = (uint32_t)(v2 * v2) | ((uint32_t)(v3 * v3) << 16);
    }
    if (tid < ROWS * 8) {
        int r = tid >> 3, o = tid & 7;
        int idx = (o < 4) ? o : (Wx + o);
        s01[r][idx] = PADSQ;
        s23[r][idx] = PADSQ;
    }
    __syncthreads();

    const float* obase = outputs + (size_t)b * Cx * SLICE + (size_t)h0 * Wx;
    const int*   tbase = targets + (size_t)b * SLICE + (size_t)h0 * Wx;

    float acc = 0.0f;
    float Sv[Cx] = {0.0f, 0.0f, 0.0f, 0.0f};
    int   Mm[Cx] = {0, 0, 0, 0};            // per-class max of m (sqrt monotone)

    #pragma unroll
    for (int ck = 0; ck < 3; ++ck) {
        int idx = ck * 512 + tid * 4;       // pixel index within band, 0..1535
        int rw  = idx / Wx;                 // warp-uniform (chunk/warp boundaries align)
        int y0  = idx - rw * Wx;            // multiple of 4

        // ---- global loads (vectorized, high MLP) ----
        const float* ob = obase + (size_t)rw * Wx + y0;
        float4 L0 = *(const float4*)(ob);
        float4 L1 = *(const float4*)(ob + SLICE);
        float4 L2 = *(const float4*)(ob + 2 * SLICE);
        float4 L3 = *(const float4*)(ob + 3 * SLICE);
        int4   T4 = *(const int4*)(tbase + (size_t)rw * Wx + y0);
        const float* l0 = &L0.x; const float* l1 = &L1.x;
        const float* l2 = &L2.x; const float* l3 = &L3.x;
        const int*   tt = &T4.x;

        // ---- window loads: indices y0..y0+11 (logical pos y0-4..y0+7) ----
        // 16B-aligned (y0 % 4 == 0), lane stride 16B -> conflict-free LDS.128
        const uint4* A4 = (const uint4*)&s01[rw][y0];
        const uint4* C4 = (const uint4*)&s23[rw][y0];
        uint4 Aa = A4[0], Ab = A4[1], Ac = A4[2];
        uint4 Ca = C4[0], Cb = C4[1], Cc = C4[2];
        uint32_t a[12] = {Aa.x, Aa.y, Aa.z, Aa.w, Ab.x, Ab.y, Ab.z, Ab.w, Ac.x, Ac.y, Ac.z, Ac.w};
        uint32_t c[12] = {Ca.x, Ca.y, Ca.z, Ca.w, Cb.x, Cb.y, Cb.z, Cb.w, Cc.x, Cc.y, Cc.z, Cc.w};

        const uint32_t K1 = 0x00010001u, K2 = 0x00040004u, K3 = 0x00090009u;
        const unsigned long long* gr = gband + (size_t)rw * Wx;

        #pragma unroll
        for (int px = 0; px < 4; ++px) {
            int i = px + 4;                 // center of pixel y0+px in window
            uint32_t m01 = a[i], m23 = c[i];
            m01 = __vminu2(m01, __vaddus2(a[i - 1], K1));
            m01 = __vminu2(m01, __vaddus2(a[i + 1], K1));
            m01 = __vminu2(m01, __vaddus2(a[i - 2], K2));
            m01 = __vminu2(m01, __vaddus2(a[i + 2], K2));
            m01 = __vminu2(m01, __vaddus2(a[i - 3], K3));
            m01 = __vminu2(m01, __vaddus2(a[i + 3], K3));
            m23 = __vminu2(m23, __vaddus2(c[i - 1], K1));
            m23 = __vminu2(m23, __vaddus2(c[i + 1], K1));
            m23 = __vminu2(m23, __vaddus2(c[i - 2], K2));
            m23 = __vminu2(m23, __vaddus2(c[i + 2], K2));
            m23 = __vminu2(m23, __vaddus2(c[i - 3], K3));
            m23 = __vminu2(m23, __vaddus2(c[i + 3], K3));

            int m0 = (int)(m01 & 0xFFFFu), m1 = (int)(m01 >> 16);
            int m2 = (int)(m23 & 0xFFFFu), m3 = (int)(m23 >> 16);
            if (__builtin_expect(max(max(m0, m1), max(m2, m3)) > 16, 0)) {  // rare
                int y = y0 + px;
                if (m0 > 16) m0 = tail_m(gr, y, 0);
                if (m1 > 16) m1 = tail_m(gr, y, 16);
                if (m2 > 16) m2 = tail_m(gr, y, 32);
                if (m3 > 16) m3 = tail_m(gr, y, 48);
            }
            float d0 = sqrt_approx((float)m0);
            float d1 = sqrt_approx((float)m1);
            float d2 = sqrt_approx((float)m2);
            float d3 = sqrt_approx((float)m3);

            float e0 = __expf(l0[px] - l3[px]);   // shift-invariant softmax, e3=1
            float e1 = __expf(l1[px] - l3[px]);
            float e2 = __expf(l2[px] - l3[px]);
            float inv = __fdividef(1.0f, e0 + e1 + e2 + 1.0f);
            int t = tt[px];

            acc += (e0 * d0 + e1 * d1 + e2 * d2 + d3) * inv;  // dt at target = 0
            Sv[0] += (t == 0) ? e0 * inv : 0.0f;
            Sv[1] += (t == 1) ? e1 * inv : 0.0f;
            Sv[2] += (t == 2) ? e2 * inv : 0.0f;
            Sv[3] += (t == 3) ? inv      : 0.0f;
            Mm[0] = max(Mm[0], m0);
            Mm[1] = max(Mm[1], m1);
            Mm[2] = max(Mm[2], m2);
            Mm[3] = max(Mm[3], m3);
        }
    }

    // block reduction (sqrt is monotone -> reduce m as int, sqrt once)
    float Lm[Cx];
    #pragma unroll
    for (int cc = 0; cc < Cx; ++cc) Lm[cc] = sqrt_approx((float)Mm[cc]);
    #pragma unroll
    for (int off = 16; off > 0; off >>= 1) {
        acc += __shfl_down_sync(0xffffffffu, acc, off);
        #pragma unroll
        for (int cc = 0; cc < Cx; ++cc) {
            Sv[cc] += __shfl_down_sync(0xffffffffu, Sv[cc], off);
            Lm[cc]  = fmaxf(Lm[cc], __shfl_down_sync(0xffffffffu, Lm[cc], off));
        }
    }
    int wid = tid >> 5;
    if ((tid & 31) == 0) {
        s_red[wid][0] = acc;
        #pragma unroll
        for (int cc = 0; cc < Cx; ++cc) { s_red[wid][1 + cc] = Sv[cc]; s_red[wid][5 + cc] = Lm[cc]; }
    }
    __syncthreads();
    if (tid < Cx) {                         // threads 0..3: one class each
        int cc = tid;
        float s = s_red[0][1 + cc] + s_red[1][1 + cc] + s_red[2][1 + cc] + s_red[3][1 + cc];
        float m = fmaxf(fmaxf(s_red[0][5 + cc], s_red[1][5 + cc]),
                        fmaxf(s_red[2][5 + cc], s_red[3][5 + cc]));
        atomicAdd(&g_S[b * Cx + cc], (double)s);
        atomicMax(&g_dmax_bits[b * Cx + cc], __float_as_uint(m));
        if (cc == 0) {
            double aa = (double)s_red[0][0] + s_red[1][0] + s_red[2][0] + s_red[3][0];
            atomicAdd(&g_acc, aa);
        }
        __threadfence();                    // release this block's contributions
    }
    __syncthreads();
    if (tid == 0)
        s_last = (atomicAdd(&g_count, 1u) == (unsigned)(gridDim.x - 1));
    __syncthreads();

    if (s_last && tid < 32) {
        __threadfence();                    // acquire all blocks' contributions
        double v = (double)__uint_as_float(((volatile unsigned int*)g_dmax_bits)[tid])
                 * ((volatile double*)g_S)[tid];
        #pragma unroll
        for (int off = 16; off > 0; off >>= 1)
            v += __shfl_down_sync(0xffffffffu, v, off);
        if (tid == 0) {
            double aa = *((volatile double*)&g_acc);
            out[0] = (float)((aa - v) / ((double)Cx * (double)Bx * Cx * Hx * Wx));
            g_count = 0u;                   // reset for next (graph) replay
        }
    }
}

// ---------------------------------------------------------------------------
extern "C" void kernel_launch(void* const* d_in, const int* in_sizes, int n_in,
                              void* d_out, int out_size) {
    const float* outputs = (const float*)d_in[0];
    const int*   targets = (const int*)d_in[1];
    float*       out     = (float*)d_out;

    k_phase1<<<Bx * (Wx / 8), 256>>>(targets);
    k_row<<<Bx * Hx / ROWS, 128>>>(outputs, targets, out);
}

// round 16
// speedup vs baseline: 1.1920x; 1.0824x over previous
#include <cuda_runtime.h>
#include <stdint.h>
#include <math.h>

#define Bx 8
#define Cx 4
#define Hx 384
#define Wx 384
#define SLICE (Hx*Wx)          // 147456
#define NSLICE (Bx*Cx)         // 32
#define BIGI 768               // = H + W, finite sentinel (matches reference)
#define INFP 0x3FFF3FFFu       // packed u16x2 "infinity" (saturating math keeps it big)
#define ONEP 0x00010001u
#define PADSQ 0xFE01FE01u      // packed 255^2 halves: pad candidates always lose (>16)
#define ROWS 4                 // rows per k_row block

// Scratch (no cudaMalloc allowed).
__device__ unsigned long long g_pack[Bx*SLICE]; // [b][h][w] -> g for 4 classes, u16x4 (9 MB)
__device__ unsigned int   g_dmax_bits[NSLICE];
__device__ double         g_S[NSLICE];          // sum of p_c over target pixels
__device__ double         g_acc;                // sum of p_c * dt over non-target pixels
__device__ unsigned int   g_count;              // zero-init; reset by last k_row block

__device__ __forceinline__ float sqrt_approx(float x) {
    float r;
    asm("sqrt.approx.f32 %0, %1;" : "=f"(r) : "f"(x));
    return r;
}

// ---------------------------------------------------------------------------
// Phase 1: vertical 1D distance per (b,w) column for ALL 4 classes packed
// u16x4. One warp per column; lane owns a 12-pixel h-segment. Exact segmented
// min-plus scan; unclamped math + final clamp(768) == reference's per-step
// clamp since increments are +1. Labels are STAGED through shared with
// coalesced int4 loads (the direct per-lane row reads were fully scattered).
__global__ void __launch_bounds__(256) k_phase1(const int* __restrict__ targets) {
    __shared__ unsigned long long sg[Hx][9];   // 27 KB staging (pad vs bank conflicts)
    __shared__ unsigned char s_t[Hx * 8];      // 3 KB label tile [h][w-w0]

    int tid = threadIdx.x, wid = tid >> 5, lane = tid & 31;
    if (blockIdx.x == 0 && tid < NSLICE) {     // fused init
        g_dmax_bits[tid] = 0u; g_S[tid] = 0.0;
        if (tid == 0) g_acc = 0.0;
    }

    int b  = blockIdx.x / (Wx / 8);
    int w0 = (blockIdx.x % (Wx / 8)) * 8;

    // coalesced staging: 768 int4 loads (3 per thread)
    {
        const int4* tp4 = (const int4*)(targets + (size_t)b * SLICE + w0);
        #pragma unroll
        for (int q = tid; q < Hx * 2; q += 256) {
            int h = q >> 1, hf = q & 1;
            int4 v = __ldg(&tp4[h * (Wx / 4) + hf]);
            int base = h * 8 + hf * 4;
            s_t[base + 0] = (unsigned char)v.x;
            s_t[base + 1] = (unsigned char)v.y;
            s_t[base + 2] = (unsigned char)v.z;
            s_t[base + 3] = (unsigned char)v.w;
        }
    }
    __syncthreads();

    int h0 = lane * 12;
    uint32_t mlo[12], mhi[12];
    #pragma unroll
    for (int i = 0; i < 12; ++i) {
        int t = s_t[(h0 + i) * 8 + wid];
        mlo[i] = (t == 0) ? 0xFFFF0000u : (t == 1) ? 0x0000FFFFu : 0xFFFFFFFFu;
        mhi[i] = (t == 2) ? 0xFFFF0000u : (t == 3) ? 0x0000FFFFu : 0xFFFFFFFFu;
    }

    uint32_t flo = INFP, fhi = INFP;
    #pragma unroll
    for (int i = 0; i < 12; ++i) { flo = __vaddus2(flo, ONEP) & mlo[i]; fhi = __vaddus2(fhi, ONEP) & mhi[i]; }
    uint32_t blo = INFP, bhi = INFP;
    #pragma unroll
    for (int i = 11; i >= 0; --i) { blo = __vaddus2(blo, ONEP) & mlo[i]; bhi = __vaddus2(bhi, ONEP) & mhi[i]; }

    uint32_t filo = flo, fihi = fhi, bilo = blo, bihi = bhi;
    #pragma unroll
    for (int d = 1; d < 32; d <<= 1) {
        uint32_t k = ((12u * d) << 16) | (12u * d);
        uint32_t a0 = __shfl_up_sync(0xffffffffu, filo, d);
        uint32_t a1 = __shfl_up_sync(0xffffffffu, fihi, d);
        if (lane >= d) { filo = __vminu2(filo, __vaddus2(a0, k)); fihi = __vminu2(fihi, __vaddus2(a1, k)); }
        uint32_t c0 = __shfl_down_sync(0xffffffffu, bilo, d);
        uint32_t c1 = __shfl_down_sync(0xffffffffu, bihi, d);
        if (lane < 32 - d) { bilo = __vminu2(bilo, __vaddus2(c0, k)); bihi = __vminu2(bihi, __vaddus2(c1, k)); }
    }
    uint32_t cflo = __shfl_up_sync(0xffffffffu, filo, 1);
    uint32_t cfhi = __shfl_up_sync(0xffffffffu, fihi, 1);
    if (lane == 0) { cflo = INFP; cfhi = INFP; }
    uint32_t cblo = __shfl_down_sync(0xffffffffu, bilo, 1);
    uint32_t cbhi = __shfl_down_sync(0xffffffffu, bihi, 1);
    if (lane == 31) { cblo = INFP; cbhi = INFP; }

    unsigned long long Df[12];
    uint32_t rlo = cflo, rhi = cfhi;
    flo = INFP; fhi = INFP;
    #pragma unroll
    for (int i = 0; i < 12; ++i) {
        rlo = __vaddus2(rlo, ONEP); rhi = __vaddus2(rhi, ONEP);
        flo = __vaddus2(flo, ONEP) & mlo[i]; fhi = __vaddus2(fhi, ONEP) & mhi[i];
        uint32_t xlo = __vminu2(flo, rlo), xhi = __vminu2(fhi, rhi);
        Df[i] = ((unsigned long long)xhi << 32) | xlo;
    }
    const uint32_t CLP = ((uint32_t)BIGI << 16) | (uint32_t)BIGI;
    rlo = cblo; rhi = cbhi; blo = INFP; bhi = INFP;
    #pragma unroll
    for (int i = 11; i >= 0; --i) {
        rlo = __vaddus2(rlo, ONEP); rhi = __vaddus2(rhi, ONEP);
        blo = __vaddus2(blo, ONEP) & mlo[i]; bhi = __vaddus2(bhi, ONEP) & mhi[i];
        uint32_t xlo = __vminu2(blo, rlo), xhi = __vminu2(bhi, rhi);
        xlo = __vminu2(__vminu2(xlo, (uint32_t)Df[i]), CLP);
        xhi = __vminu2(__vminu2(xhi, (uint32_t)(Df[i] >> 32)), CLP);
        sg[h0 + i][wid] = ((unsigned long long)xhi << 32) | xlo;
    }
    __syncthreads();

    unsigned long long* gp = g_pack + (size_t)b * SLICE;
    #pragma unroll
    for (int e = tid; e < Hx * 8; e += 256) {
        int h = e >> 3, wl = e & 7;
        gp[(size_t)h * Wx + w0 + wl] = sg[h][wl];
    }
}

// ---------------------------------------------------------------------------
// Rare exact tail for m > 16: full pruned scan from global packed g.
__device__ __noinline__ int tail_m(const unsigned long long* gr, int y, int sh) {
    int v0 = (int)((gr[y] >> sh) & 0xFFFF);
    int m = v0 * v0;
    for (int r = 1; r < Wx && r * r < m; ++r) {
        int jl = y - r, jr = y + r;
        if (jl >= 0) { int v = (int)((gr[jl] >> sh) & 0xFFFF); m = min(m, v * v + r * r); }
        if (jr < Wx) { int v = (int)((gr[jr] >> sh) & 0xFFFF); m = min(m, v * v + r * r); }
    }
    return m;
}

// ---------------------------------------------------------------------------
// One pixel, fully register-explicit (no pointer-indexed register access --
// that pattern forces local-memory demotion). Window args are named uint32
// components; logits are named float components.
#define PIX(a3m,a2m,a1m,a0_,a1p,a2p,a3p, c3m,c2m,c1m,c0_,c1p,c2p,c3p, lx0,lx1,lx2,lx3, tx, yy) do { \
    uint32_t m01 = (a0_), m23 = (c0_);                                        \
    m01 = __vminu2(m01, __vaddus2((a1m), K1));                                \
    m01 = __vminu2(m01, __vaddus2((a1p), K1));                                \
    m01 = __vminu2(m01, __vaddus2((a2m), K2));                                \
    m01 = __vminu2(m01, __vaddus2((a2p), K2));                                \
    m01 = __vminu2(m01, __vaddus2((a3m), K3));                                \
    m01 = __vminu2(m01, __vaddus2((a3p), K3));                                \
    m23 = __vminu2(m23, __vaddus2((c1m), K1));                                \
    m23 = __vminu2(m23, __vaddus2((c1p), K1));                                \
    m23 = __vminu2(m23, __vaddus2((c2m), K2));                                \
    m23 = __vminu2(m23, __vaddus2((c2p), K2));                                \
    m23 = __vminu2(m23, __vaddus2((c3m), K3));                                \
    m23 = __vminu2(m23, __vaddus2((c3p), K3));                                \
    int m0 = (int)(m01 & 0xFFFFu), m1 = (int)(m01 >> 16);                     \
    int m2 = (int)(m23 & 0xFFFFu), m3 = (int)(m23 >> 16);                     \
    if (__builtin_expect(max(max(m0, m1), max(m2, m3)) > 16, 0)) {            \
        if (m0 > 16) m0 = tail_m(gr, (yy), 0);                                \
        if (m1 > 16) m1 = tail_m(gr, (yy), 16);                               \
        if (m2 > 16) m2 = tail_m(gr, (yy), 32);                               \
        if (m3 > 16) m3 = tail_m(gr, (yy), 48);                               \
    }                                                                         \
    float d0 = sqrt_approx((float)m0);                                        \
    float d1 = sqrt_approx((float)m1);                                        \
    float d2 = sqrt_approx((float)m2);                                        \
    float d3 = sqrt_approx((float)m3);                                        \
    float e0 = __expf((lx0) - (lx3));                                         \
    float e1 = __expf((lx1) - (lx3));                                         \
    float e2 = __expf((lx2) - (lx3));                                         \
    float inv = __fdividef(1.0f, e0 + e1 + e2 + 1.0f);                        \
    acc += (e0 * d0 + e1 * d1 + e2 * d2 + d3) * inv;                          \
    Sv0 += ((tx) == 0) ? e0 * inv : 0.0f;                                     \
    Sv1 += ((tx) == 1) ? e1 * inv : 0.0f;                                     \
    Sv2 += ((tx) == 2) ? e2 * inv : 0.0f;                                     \
    Sv3 += ((tx) == 3) ? inv      : 0.0f;                                     \
    Mm0 = max(Mm0, m0); Mm1 = max(Mm1, m1);                                   \
    Mm2 = max(Mm2, m2); Mm3 = max(Mm3, m3);                                   \
} while (0)

// ---------------------------------------------------------------------------
// Phase 2+3 fused + finalization: one 128-thread block per (b, 4-row band).
// Each thread handles 4 CONSECUTIVE pixels -> float4/int4 global loads; the
// overlapping radius-3 windows are covered by 3 aligned uint4 LDS.128 per
// class-pair array (conflict-free). All intermediates are named registers.
//   dt_c(y) = sqrt( min_j g_c(j)^2 + (y-j)^2 )
// Fast path: min over |r|<=3 of min(g,255)^2 + r^2 via u16x2 SIMD. Exact when
// m <= 16 (every excluded candidate -- r>=4 or clamped g>=255 -- has value
// >= 16; ties at 16 leave the min unchanged); else rare exact tail (~0.03%).
// Softmax shifted by l3 (e3 = 1, shift-invariant). dt at target class is 0.
// Last block (counter) finalizes:
//   loss = ( sum p_c*dt_c - sum_s dmax_s*S_s ) / (C * B*C*H*W).
__global__ void __launch_bounds__(128, 6) k_row(const float* __restrict__ outputs,
                                                const int*   __restrict__ targets,
                                                float*       __restrict__ out) {
    __shared__ uint32_t s01[ROWS][Wx + 8];   // sq(c0)|sq(c1)<<16, +-4 pad; 6.1 KB
    __shared__ uint32_t s23[ROWS][Wx + 8];   // sq(c2)|sq(c3)<<16
    __shared__ float s_red[4][9];
    __shared__ int s_last;

    int tid  = threadIdx.x;
    int band = blockIdx.x;             // 0 .. B*H/ROWS-1
    int b    = band / (Hx / ROWS);
    int h0   = (band % (Hx / ROWS)) * ROWS;

    const unsigned long long* gband = g_pack + (size_t)b * SLICE + (size_t)h0 * Wx;

    // build clamped-square packed arrays for the 4 rows
    for (int i = tid; i < ROWS * Wx; i += 128) {
        int r = i / Wx, x = i - r * Wx;
        unsigned long long v = gband[i];
        int v0 = min((int)(v & 0xFFFF), 255);
        int v1 = min((int)((v >> 16) & 0xFFFF), 255);
        int v2 = min((int)((v >> 32) & 0xFFFF), 255);
        int v3 = min((int)((v >> 48) & 0xFFFF), 255);
        s01[r][4 + x] = (uint32_t)(v0 * v0) | ((uint32_t)(v1 * v1) << 16);
        s23[r][4 + x] = (uint32_t)(v2 * v2) | ((uint32_t)(v3 * v3) << 16);
    }
    if (tid < ROWS * 8) {
        int r = tid >> 3, o = tid & 7;
        int idx = (o < 4) ? o : (Wx + o);
        s01[r][idx] = PADSQ;
        s23[r][idx] = PADSQ;
    }
    __syncthreads();

    const float* obase = outputs + (size_t)b * Cx * SLICE + (size_t)h0 * Wx;
    const int*   tbase = targets + (size_t)b * SLICE + (size_t)h0 * Wx;

    float acc = 0.0f;
    float Sv0 = 0.0f, Sv1 = 0.0f, Sv2 = 0.0f, Sv3 = 0.0f;
    int   Mm0 = 0, Mm1 = 0, Mm2 = 0, Mm3 = 0;
    const uint32_t K1 = 0x00010001u, K2 = 0x00040004u, K3 = 0x00090009u;

    #pragma unroll
    for (int ck = 0; ck < 3; ++ck) {
        int idx = ck * 512 + tid * 4;       // pixel index within band, 0..1535
        int rw  = idx / Wx;                 // warp-uniform (chunk/warp boundaries align)
        int y0  = idx - rw * Wx;            // multiple of 4

        // ---- global loads (vectorized, high MLP) ----
        const float* ob = obase + (size_t)rw * Wx + y0;
        float4 L0 = *(const float4*)(ob);
        float4 L1 = *(const float4*)(ob + SLICE);
        float4 L2 = *(const float4*)(ob + 2 * SLICE);
        float4 L3 = *(const float4*)(ob + 3 * SLICE);
        int4   T4 = *(const int4*)(tbase + (size_t)rw * Wx + y0);

        // ---- window loads: logical positions y0-4 .. y0+7, 16B-aligned ----
        const uint4* A4 = (const uint4*)&s01[rw][y0];
        const uint4* C4 = (const uint4*)&s23[rw][y0];
        uint4 Aa = A4[0], Ab = A4[1], Ac = A4[2];
        uint4 Ca = C4[0], Cb = C4[1], Cc = C4[2];

        const unsigned long long* gr = gband + (size_t)rw * Wx;

        PIX(Aa.y, Aa.z, Aa.w, Ab.x, Ab.y, Ab.z, Ab.w,
            Ca.y, Ca.z, Ca.w, Cb.x, Cb.y, Cb.z, Cb.w,
            L0.x, L1.x, L2.x, L3.x, T4.x, y0 + 0);
        PIX(Aa.z, Aa.w, Ab.x, Ab.y, Ab.z, Ab.w, Ac.x,
            Ca.z, Ca.w, Cb.x, Cb.y, Cb.z, Cb.w, Cc.x,
            L0.y, L1.y, L2.y, L3.y, T4.y, y0 + 1);
        PIX(Aa.w, Ab.x, Ab.y, Ab.z, Ab.w, Ac.x, Ac.y,
            Ca.w, Cb.x, Cb.y, Cb.z, Cb.w, Cc.x, Cc.y,
            L0.z, L1.z, L2.z, L3.z, T4.z, y0 + 2);
        PIX(Ab.x, Ab.y, Ab.z, Ab.w, Ac.x, Ac.y, Ac.z,
            Cb.x, Cb.y, Cb.z, Cb.w, Cc.x, Cc.y, Cc.z,
            L0.w, L1.w, L2.w, L3.w, T4.w, y0 + 3);
    }

    // block reduction (sqrt is monotone -> reduce m as int, sqrt once)
    float Lm0 = sqrt_approx((float)Mm0);
    float Lm1 = sqrt_approx((float)Mm1);
    float Lm2 = sqrt_approx((float)Mm2);
    float Lm3 = sqrt_approx((float)Mm3);
    #pragma unroll
    for (int off = 16; off > 0; off >>= 1) {
        acc += __shfl_down_sync(0xffffffffu, acc, off);
        Sv0 += __shfl_down_sync(0xffffffffu, Sv0, off);
        Sv1 += __shfl_down_sync(0xffffffffu, Sv1, off);
        Sv2 += __shfl_down_sync(0xffffffffu, Sv2, off);
        Sv3 += __shfl_down_sync(0xffffffffu, Sv3, off);
        Lm0  = fmaxf(Lm0, __shfl_down_sync(0xffffffffu, Lm0, off));
        Lm1  = fmaxf(Lm1, __shfl_down_sync(0xffffffffu, Lm1, off));
        Lm2  = fmaxf(Lm2, __shfl_down_sync(0xffffffffu, Lm2, off));
        Lm3  = fmaxf(Lm3, __shfl_down_sync(0xffffffffu, Lm3, off));
    }
    int wid = tid >> 5;
    if ((tid & 31) == 0) {
        s_red[wid][0] = acc;
        s_red[wid][1] = Sv0; s_red[wid][2] = Sv1; s_red[wid][3] = Sv2; s_red[wid][4] = Sv3;
        s_red[wid][5] = Lm0; s_red[wid][6] = Lm1; s_red[wid][7] = Lm2; s_red[wid][8] = Lm3;
    }
    __syncthreads();
    if (tid < Cx) {                         // threads 0..3: one class each
        int cc = tid;
        float s = s_red[0][1 + cc] + s_red[1][1 + cc] + s_red[2][1 + cc] + s_red[3][1 + cc];
        float m = fmaxf(fmaxf(s_red[0][5 + cc], s_red[1][5 + cc]),
                        fmaxf(s_red[2][5 + cc], s_red[3][5 + cc]));
        atomicAdd(&g_S[b * Cx + cc], (double)s);
        atomicMax(&g_dmax_bits[b * Cx + cc], __float_as_uint(m));
        if (cc == 0) {
            double aa = (double)s_red[0][0] + s_red[1][0] + s_red[2][0] + s_red[3][0];
            atomicAdd(&g_acc, aa);
        }
        __threadfence();                    // release this block's contributions
    }
    __syncthreads();
    if (tid == 0)
        s_last = (atomicAdd(&g_count, 1u) == (unsigned)(gridDim.x - 1));
    __syncthreads();

    if (s_last && tid < 32) {
        __threadfence();                    // acquire all blocks' contributions
        double v = (double)__uint_as_float(((volatile unsigned int*)g_dmax_bits)[tid])
                 * ((volatile double*)g_S)[tid];
        #pragma unroll
        for (int off = 16; off > 0; off >>= 1)
            v += __shfl_down_sync(0xffffffffu, v, off);
        if (tid == 0) {
            double aa = *((volatile double*)&g_acc);
            out[0] = (float)((aa - v) / ((double)Cx * (double)Bx * Cx * Hx * Wx));
            g_count = 0u;                   // reset for next (graph) replay
        }
    }
}

// ---------------------------------------------------------------------------
extern "C" void kernel_launch(void* const* d_in, const int* in_sizes, int n_in,
                              void* d_out, int out_size) {
    const float* outputs = (const float*)d_in[0];
    const int*   targets = (const int*)d_in[1];
    float*       out     = (float*)d_out;

    k_phase1<<<Bx * (Wx / 8), 256>>>(targets);
    k_row<<<Bx * Hx / ROWS, 128>>>(outputs, targets, out);
}